// round 13
// baseline (speedup 1.0000x reference)
#include <cuda_runtime.h>
#include <cuda_bf16.h>
#include <math.h>

#define BATCH 1024
#define SEQ   1024
#define TAGS  32
#define ITERS 511          // main-loop iterations per direction
#define PF    8            // emit prefetch ring depth

__device__ float g_logz[BATCH];
__device__ float g_partial[BATCH];
__device__ unsigned int g_ticket;

__device__ __forceinline__ float ex2f(float x) {
    float y; asm("ex2.approx.f32 %0, %1;" : "=f"(y) : "f"(x)); return y;
}
__device__ __forceinline__ float lg2f(float x) {
    float y; asm("lg2.approx.f32 %0, %1;" : "=f"(y) : "f"(x)); return y;
}
__device__ __forceinline__ float rcpf(float x) {
    float y; asm("rcp.approx.f32 %0, %1;" : "=f"(y) : "f"(x)); return y;
}

#define LOG2E 1.4426950408889634f
#define LN2   0.6931471805599453f

// Butterfly all-gather matvec: every lane receives all 32 w-values via 31
// shfl.xor (5 doubling levels — information-theoretic minimum), then 32 FFMA
// onto 4 accumulators. v[p] = w[lane ^ bitrev5(p)]; caller pre-permutes er[]
// to match. No STS / WARPSYNC / LDS in the loop — pure SHFL+FMA pipes.
__device__ __forceinline__ float bfly_matvec(float u, const float* er) {
    float v[32];
    v[0] = u;
    v[1] = __shfl_xor_sync(0xffffffffu, v[0], 16);
#pragma unroll
    for (int q = 0; q < 2; q++)  v[2 + q]  = __shfl_xor_sync(0xffffffffu, v[q], 8);
#pragma unroll
    for (int q = 0; q < 4; q++)  v[4 + q]  = __shfl_xor_sync(0xffffffffu, v[q], 4);
#pragma unroll
    for (int q = 0; q < 8; q++)  v[8 + q]  = __shfl_xor_sync(0xffffffffu, v[q], 2);
#pragma unroll
    for (int q = 0; q < 16; q++) v[16 + q] = __shfl_xor_sync(0xffffffffu, v[q], 1);

    float s0 = v[0] * er[0];
    float s1 = v[1] * er[1];
    float s2 = v[2] * er[2];
    float s3 = v[3] * er[3];
#pragma unroll
    for (int p = 4; p < 32; p += 4) {
        s0 = fmaf(v[p],     er[p],     s0);
        s1 = fmaf(v[p + 1], er[p + 1], s1);
        s2 = fmaf(v[p + 2], er[p + 2], s2);
        s3 = fmaf(v[p + 3], er[p + 3], s3);
    }
    return (s0 + s1) + (s2 + s3);
}

// ---------------------------------------------------------------------------
// Forward+backward kernel: 1 chain per warp, 2048 warps.
// 2 batches per block (128 threads):
//   warp 0: fwd b0   warp 1: bwd b0   warp 2: fwd b1   warp 3: bwd b1
// Probability-space recursion, renorm every 4 steps (lane-0 broadcast).
// Matvec via register-only butterfly gather (no smem in the hot loop).
// Meet: Z = sum_k (E^T alpha_511)_k gamma_512(k)
// ---------------------------------------------------------------------------
__global__ __launch_bounds__(128, 4)
void crf_fb_kernel(const float* __restrict__ logits,
                   const float* __restrict__ trans) {
    const int w   = threadIdx.x >> 5;     // warp in block (0..3)
    const int j   = threadIdx.x & 31;     // lane = tag
    const int bi  = w >> 1;               // batch within block (0/1)
    const int dir = w & 1;                // 0 = fwd, 1 = bwd
    const int b   = blockIdx.x * 2 + bi;

    __shared__ float xg[2][32];           // gamma_512 exchange
    __shared__ float xacc[2];             // bwd log-scale exchange

    // er[p] = exp(trans) permuted for the butterfly gather order:
    //   fwd (lane = dest tag j):   er[p] = E[j ^ bitrev5(p)][j]
    //   bwd (lane = src tag i=j):  er[p] = E[j][j ^ bitrev5(p)]
    float er[32];
#pragma unroll
    for (int p = 0; p < 32; p++) {
        int rb = ((p & 1) << 4) | ((p & 2) << 2) | (p & 4)
               | ((p & 8) >> 2) | ((p & 16) >> 4);   // bitrev5(p)
        int i = j ^ rb;
        er[p] = expf((dir == 0) ? trans[i * TAGS + j]
                                : trans[j * TAGS + i]);
    }

    const float* lg = logits + (size_t)b * (SEQ * TAGS);

    // init state (scaled by lane-0 emit)
    float e0 = (dir == 0) ? lg[j] : lg[(SEQ - 1) * TAGS + j];
    float m0 = __shfl_sync(0xffffffffu, e0, 0);
    float u      = ex2f((e0 - m0) * LOG2E);
    float logacc = m0;

    // emit stream: fwd rows 1..511, bwd rows 1022..512.
    // Ring depth PF=8; tail over-reads stay in-bounds (fwd<=519, bwd>=504).
    const int estep = (dir == 0) ? TAGS : -TAGS;
    const float* ep = (dir == 0) ? (lg + TAGS + j)
                                 : (lg + (SEQ - 2) * TAGS + j);
    float r[PF];
#pragma unroll
    for (int k = 0; k < PF; k++)
        r[k] = ep[k * estep];
    const float* pl = ep + PF * estep;

#pragma unroll 8
    for (int it = 0; it < ITERS; ++it) {
        float emit = r[it & (PF - 1)];
        r[it & (PF - 1)] = *pl;             // refill same slot (needed it+8)
        pl += estep;

        float p = ex2f(emit * LOG2E);       // off the carried chain

        float s = bfly_matvec(u, er);       // 31 shfl + 32 ffma, sync-free
        float un = s * p;

        if ((it & 3) == 0) {
            float u0 = __shfl_sync(0xffffffffu, u, 0);  // uniform branch
            un *= rcpf(u0);
            logacc += lg2f(u0) * LN2;       // off-path bookkeeping
        }
        u = un;
    }

    // final renorm so the meeting dot-product can't overflow
    {
        float u0 = __shfl_sync(0xffffffffu, u, 0);
        u *= rcpf(u0);
        logacc += lg2f(u0) * LN2;
    }

    if (dir == 1) {
        xg[bi][j] = u;                      // gamma_512 (scaled)
        if (j == 0) xacc[bi] = logacc;
    }
    __syncthreads();

    if (dir == 0) {
        // s = E^T alpha_511 (one more matvec, no emit)
        float s = bfly_matvec(u, er);

        float prod = s * xg[bi][j];
#pragma unroll
        for (int k = 16; k; k >>= 1)
            prod += __shfl_xor_sync(0xffffffffu, prod, k);

        if (j == 0)
            g_logz[b] = lg2f(prod) * LN2 + logacc + xacc[bi];
    }
}

// ---------------------------------------------------------------------------
// Gold score: one 256-thread block per batch (2x R12's warps for gather-
// latency hiding; gold was one-wave grid-limited at 128 threads). The LAST
// block also performs the final deterministic reduction (threadfence-ticket);
// ticket reset keeps graph replays deterministic.
// ---------------------------------------------------------------------------
__global__ __launch_bounds__(256, 4)
void crf_gold_reduce_kernel(const float* __restrict__ logits,
                            const float* __restrict__ trans,
                            const int* __restrict__ tags,
                            const int* __restrict__ lengths,
                            float* __restrict__ out) {
    __shared__ float tr[TAGS * TAGS];
    __shared__ float sm[8];
    __shared__ bool  amLast;

    for (int i = threadIdx.x; i < TAGS * TAGS; i += blockDim.x)
        tr[i] = trans[i];
    __syncthreads();

    const int b    = blockIdx.x;
    const int tid  = threadIdx.x;
    const int warp = tid >> 5;
    const int l    = tid & 31;

    const int*   tg = tags + (size_t)b * SEQ;
    const float* lg = logits + (size_t)b * (SEQ * TAGS);
    const int len = lengths[b];

    float acc = 0.0f;
    for (int s = tid; s < len; s += 256) {
        int t1 = __ldg(&tg[s]);
        acc += __ldg(&lg[s * TAGS + t1]);
        if (s > 0) {
            int t0 = __ldg(&tg[s - 1]);
            acc += tr[t0 * TAGS + t1];
        }
    }
#pragma unroll
    for (int k = 16; k; k >>= 1)
        acc += __shfl_xor_sync(0xffffffffu, acc, k);
    if (l == 0) sm[warp] = acc;
    __syncthreads();

    if (tid == 0) {
        float gold = 0.0f;
#pragma unroll
        for (int q = 0; q < 8; q++) gold += sm[q];
        g_partial[b] = g_logz[b] - gold;
        __threadfence();
        unsigned int t = atomicAdd(&g_ticket, 1u);
        amLast = (t == (unsigned)(BATCH - 1));
    }
    __syncthreads();

    if (amLast) {
        __shared__ float red[256];
        float a = 0.0f;
#pragma unroll
        for (int o = 0; o < 4; o++)
            a += __ldcg(&g_partial[tid + o * 256]);
        red[tid] = a;
        __syncthreads();
#pragma unroll
        for (int k = 128; k; k >>= 1) {
            if (tid < k) red[tid] += red[tid + k];
            __syncthreads();
        }
        if (tid == 0) {
            out[0] = red[0] * (1.0f / 1024.0f);
            g_ticket = 0;                  // reset for next graph replay
        }
    }
}

extern "C" void kernel_launch(void* const* d_in, const int* in_sizes, int n_in,
                              void* d_out, int out_size) {
    const float* logits  = (const float*)d_in[0];
    const float* trans   = (const float*)d_in[1];
    const int*   tags    = (const int*)d_in[2];
    const int*   lengths = (const int*)d_in[3];
    float* out = (float*)d_out;

    crf_fb_kernel<<<BATCH / 2, 128>>>(logits, trans);
    crf_gold_reduce_kernel<<<BATCH, 256>>>(logits, trans, tags, lengths, out);
}

// round 14
// speedup vs baseline: 1.3904x; 1.3904x over previous
#include <cuda_runtime.h>
#include <cuda_bf16.h>
#include <math.h>

#define BATCH 1024
#define SEQ   1024
#define TAGS  32
#define ITERS 511          // main-loop iterations per direction
#define PF    8            // emit prefetch ring depth

__device__ float g_partial[BATCH];
__device__ unsigned int g_ticket;

// ---------- packed f32x2 helpers (sm_103a FFMA2 path, PTX-only) ----------
__device__ __forceinline__ unsigned long long pk2(float x, float y) {
    unsigned long long r;
    asm("mov.b64 %0, {%1, %2};" : "=l"(r) : "f"(x), "f"(y));
    return r;
}
__device__ __forceinline__ void upk2(unsigned long long a, float& x, float& y) {
    asm("mov.b64 {%0, %1}, %2;" : "=f"(x), "=f"(y) : "l"(a));
}
__device__ __forceinline__ unsigned long long mul2(unsigned long long a, unsigned long long b) {
    unsigned long long d;
    asm("mul.rn.f32x2 %0, %1, %2;" : "=l"(d) : "l"(a), "l"(b));
    return d;
}
__device__ __forceinline__ unsigned long long fma2(unsigned long long a, unsigned long long b, unsigned long long c) {
    unsigned long long d;
    asm("fma.rn.f32x2 %0, %1, %2, %3;" : "=l"(d) : "l"(a), "l"(b), "l"(c));
    return d;
}
__device__ __forceinline__ unsigned long long add2(unsigned long long a, unsigned long long b) {
    unsigned long long d;
    asm("add.rn.f32x2 %0, %1, %2;" : "=l"(d) : "l"(a), "l"(b));
    return d;
}
__device__ __forceinline__ float ex2f(float x) {
    float y; asm("ex2.approx.f32 %0, %1;" : "=f"(y) : "f"(x)); return y;
}
__device__ __forceinline__ float lg2f(float x) {
    float y; asm("lg2.approx.f32 %0, %1;" : "=f"(y) : "f"(x)); return y;
}
__device__ __forceinline__ float rcpf(float x) {
    float y; asm("rcp.approx.f32 %0, %1;" : "=f"(y) : "f"(x)); return y;
}

#define LOG2E 1.4426950408889634f
#define LN2   0.6931471805599453f

// shared matvec: s_j = sum_i w_i * e-pairs. Returns w0 (= wb[0]) from the
// already-loaded q0 register so renorm never issues an extra on-chain LDS.
__device__ __forceinline__ float matvec32(const float* wb,
                                          const unsigned long long* e,
                                          float& w0_out) {
    const ulonglong2* w4 = (const ulonglong2*)wb;
    ulonglong2 q0 = w4[0], q1 = w4[1], q2 = w4[2], q3 = w4[3];
    {
        float a, bdum; upk2(q0.x, a, bdum); w0_out = a;
    }
    unsigned long long a0 = mul2(q0.x, e[0]);
    unsigned long long a1 = mul2(q0.y, e[1]);
    unsigned long long a2 = mul2(q1.x, e[2]);
    unsigned long long a3 = mul2(q1.y, e[3]);
    a0 = fma2(q2.x, e[4], a0);
    a1 = fma2(q2.y, e[5], a1);
    a2 = fma2(q3.x, e[6], a2);
    a3 = fma2(q3.y, e[7], a3);
    ulonglong2 q4 = w4[4], q5 = w4[5], q6 = w4[6], q7 = w4[7];
    a0 = fma2(q4.x, e[8],  a0);
    a1 = fma2(q4.y, e[9],  a1);
    a2 = fma2(q5.x, e[10], a2);
    a3 = fma2(q5.y, e[11], a3);
    a0 = fma2(q6.x, e[12], a0);
    a1 = fma2(q6.y, e[13], a1);
    a2 = fma2(q7.x, e[14], a2);
    a3 = fma2(q7.y, e[15], a3);
    a0 = add2(a0, a1);
    a2 = add2(a2, a3);
    a0 = add2(a0, a2);
    float slo, shi;
    upk2(a0, slo, shi);
    return slo + shi;
}

// ---------------------------------------------------------------------------
// Fully fused CRF kernel. 2 batches per block (128 threads):
//   warp 0: fwd b0   warp 1: bwd b0   warp 2: fwd b1   warp 3: bwd b1
// Forward/backward prob-space scans (R12 smem matvec — fastest measured).
// GOLD SCORE computed inline: at iter t the warp's `emit` registers hold
// logits row t, so logits[t, tags[t]] is one shfl.idx away; tags stream
// loads coalesced once per 32-iter chunk. fwd covers s=0..511, bwd 512..1023.
// Last block does the ticket-fenced deterministic reduction -> mean.
// ---------------------------------------------------------------------------
__global__ __launch_bounds__(128, 4)
void crf_fused_kernel(const float* __restrict__ logits,
                      const float* __restrict__ trans,
                      const int* __restrict__ tags,
                      const int* __restrict__ lengths,
                      float* __restrict__ out) {
    const int w   = threadIdx.x >> 5;     // warp in block (0..3)
    const int j   = threadIdx.x & 31;     // lane = tag
    const int bi  = w >> 1;               // batch within block (0/1)
    const int dir = w & 1;                // 0 = fwd, 1 = bwd
    const int b   = blockIdx.x * 2 + bi;

    __shared__ __align__(16) float sbuf[4][2][32];  // [warp][parity][vec]
    __shared__ float tr_s[TAGS * TAGS];             // raw trans (gold lookups)
    __shared__ float xg[2][32];                     // gamma_512 exchange
    __shared__ float xacc[2];                       // bwd log-scale exchange
    __shared__ float gacc[4];                       // per-warp gold partials
    __shared__ bool  amLast;

    for (int i = threadIdx.x; i < TAGS * TAGS; i += 128)
        tr_s[i] = trans[i];

    // E operand registers (pairs packed for fma2):
    //  fwd: e[k] = { E[2k][j],  E[2k+1][j] }   (pairs over i, column j)
    //  bwd: e[k] = { E[j][2k],  E[j][2k+1] }   (pairs over j', row i=lane)
    unsigned long long e[16];
    if (dir == 0) {
#pragma unroll
        for (int k = 0; k < 16; k++)
            e[k] = pk2(expf(trans[(2 * k)     * TAGS + j]),
                       expf(trans[(2 * k + 1) * TAGS + j]));
    } else {
#pragma unroll
        for (int k = 0; k < 16; k++)
            e[k] = pk2(expf(trans[j * TAGS + 2 * k]),
                       expf(trans[j * TAGS + 2 * k + 1]));
    }
    __syncthreads();                       // tr_s ready before gold lookups

    const float* lg = logits + (size_t)b * (SEQ * TAGS);
    const int*   tg = tags   + (size_t)b * SEQ;
    const int    len = lengths[b];

    // init state (scaled by lane-0 emit)
    float e0 = (dir == 0) ? lg[j] : lg[(SEQ - 1) * TAGS + j];
    float m0 = __shfl_sync(0xffffffffu, e0, 0);
    float u      = ex2f((e0 - m0) * LOG2E);
    float logacc = m0;

    // ---- gold: boundary contributions handled at init ----
    float gold = 0.0f;
    if (dir == 0) {
        int t0v = tg[0];                                   // broadcast load
        float g0 = __shfl_sync(0xffffffffu, e0, t0v);      // logits[0, tags[0]]
        if (j == 0) gold += g0;                            // s=0 < len always
    } else {
        int t1023 = tg[SEQ - 1];
        int t1022 = tg[SEQ - 2];
        float g1 = __shfl_sync(0xffffffffu, e0, t1023);    // logits[1023, tags[1023]]
        if (j == 0 && (SEQ - 1) < len)
            gold += g1 + tr_s[t1022 * TAGS + t1023];       // pair (1022,1023)
    }

    // emit stream: fwd rows 1..511, bwd rows 1022..512.
    // Ring depth PF=8; tail over-reads stay in-bounds (fwd<=519, bwd>=504).
    const int estep = (dir == 0) ? TAGS : -TAGS;
    const float* ep = (dir == 0) ? (lg + TAGS + j)
                                 : (lg + (SEQ - 2) * TAGS + j);
    float r[PF];
#pragma unroll
    for (int k = 0; k < PF; k++)
        r[k] = ep[k * estep];
    const float* pl = ep + PF * estep;

    // gold tag chunks: lane l handles s = (fwd: it0+1+l | bwd: 1022-it0-l)
    // at iter it = it0 + l. tcur/tprev loaded coalesced once per 32 iters.
    const int* ptag = (dir == 0) ? (tg + 1 + j) : (tg + (SEQ - 2) - j);
    const int tagstep = (dir == 0) ? 1 : -1;
    int   tcur = 0;
    float ts   = 0.0f;                     // trans[tags[s-1], tags[s]]
    int   sg   = 0;                        // this lane's s for current chunk

#pragma unroll 8
    for (int it = 0; it < ITERS; ++it) {
        if ((it & 31) == 0) {              // uniform branch, once per 32 iters
            tcur = ptag[it * tagstep];
            int tprev = ptag[(it - 1) * tagstep];
            ts = tr_s[tprev * TAGS + tcur];
            sg = (dir == 0) ? (it + 1 + j) : (SEQ - 2 - it - j);
        }

        float emit = r[it & (PF - 1)];
        r[it & (PF - 1)] = *pl;            // refill same slot (needed it+8)
        pl += estep;

        // ---- gold: one shfl + predicated add, rides in issue holes ----
        float gv = __shfl_sync(0xffffffffu, emit, tcur);
        if (((it & 31) == j) && (sg < len))
            gold += gv + ts;

        float p = ex2f(emit * LOG2E);      // off the carried chain

        float* wb = &sbuf[w][it & 1][0];
        wb[j] = u;
        __syncwarp(0xffffffffu);

        float w0;
        float s = matvec32(wb, e, w0);
        float un = s * p;

        if ((it & 3) == 0) {
            un *= rcpf(w0);                // w0 from matvec's q0 register
            logacc += lg2f(w0) * LN2;      // off-path bookkeeping
        }
        u = un;
    }

    // final renorm so the meeting dot-product can't overflow
    {
        float u0 = __shfl_sync(0xffffffffu, u, 0);
        u *= rcpf(u0);
        logacc += lg2f(u0) * LN2;
    }

    // per-warp gold partial -> smem
#pragma unroll
    for (int k = 16; k; k >>= 1)
        gold += __shfl_xor_sync(0xffffffffu, gold, k);
    if (j == 0) gacc[w] = gold;

    if (dir == 1) {
        xg[bi][j] = u;                     // gamma_512 (scaled)
        if (j == 0) xacc[bi] = logacc;
    }
    __syncthreads();

    if (dir == 0) {
        // s = E^T alpha_511 (one more matvec, no emit). Parity-1 buffer:
        // its last reads (it=509) are sealed by syncwarp(it=510).
        float* wb1 = &sbuf[w][1][0];
        wb1[j] = u;
        __syncwarp(0xffffffffu);
        float w0d;
        float s = matvec32(wb1, e, w0d);

        float prod = s * xg[bi][j];
#pragma unroll
        for (int k = 16; k; k >>= 1)
            prod += __shfl_xor_sync(0xffffffffu, prod, k);

        if (j == 0) {
            float logz = lg2f(prod) * LN2 + logacc + xacc[bi];
            g_partial[b] = logz - (gacc[w] + gacc[w + 1]);
            __threadfence();               // writer-side fence before ticket
        }
    }
    __syncthreads();

    // ---- last block performs the deterministic final reduction ----
    if (threadIdx.x == 0) {
        unsigned int t = atomicAdd(&g_ticket, 1u);
        amLast = (t == (unsigned)(BATCH / 2 - 1));
    }
    __syncthreads();

    if (amLast) {
        __shared__ float red[128];
        const int tid = threadIdx.x;
        float a = 0.0f;
#pragma unroll
        for (int o = 0; o < 8; o++)
            a += __ldcg(&g_partial[tid + o * 128]);
        red[tid] = a;
        __syncthreads();
#pragma unroll
        for (int k = 64; k; k >>= 1) {
            if (tid < k) red[tid] += red[tid + k];
            __syncthreads();
        }
        if (tid == 0) {
            out[0] = red[0] * (1.0f / 1024.0f);
            g_ticket = 0;                  // reset for next graph replay
        }
    }
}

extern "C" void kernel_launch(void* const* d_in, const int* in_sizes, int n_in,
                              void* d_out, int out_size) {
    const float* logits  = (const float*)d_in[0];
    const float* trans   = (const float*)d_in[1];
    const int*   tags    = (const int*)d_in[2];
    const int*   lengths = (const int*)d_in[3];
    float* out = (float*)d_out;

    crf_fused_kernel<<<BATCH / 2, 128>>>(logits, trans, tags, lengths, out);
}

// round 15
// speedup vs baseline: 1.5243x; 1.0963x over previous
#include <cuda_runtime.h>
#include <cuda_bf16.h>
#include <math.h>

#define BATCH 1024
#define SEQ   1024
#define TAGS  32
#define ITERS 511          // main-loop iterations per direction
#define PF    8            // emit prefetch ring depth

__device__ float g_logz[BATCH];
__device__ float g_partial[BATCH];
__device__ unsigned int g_ticket;

// ---------- packed f32x2 helpers (sm_103a FFMA2 path, PTX-only) ----------
__device__ __forceinline__ unsigned long long pk2(float x, float y) {
    unsigned long long r;
    asm("mov.b64 %0, {%1, %2};" : "=l"(r) : "f"(x), "f"(y));
    return r;
}
__device__ __forceinline__ void upk2(unsigned long long a, float& x, float& y) {
    asm("mov.b64 {%0, %1}, %2;" : "=f"(x), "=f"(y) : "l"(a));
}
__device__ __forceinline__ unsigned long long mul2(unsigned long long a, unsigned long long b) {
    unsigned long long d;
    asm("mul.rn.f32x2 %0, %1, %2;" : "=l"(d) : "l"(a), "l"(b));
    return d;
}
__device__ __forceinline__ unsigned long long fma2(unsigned long long a, unsigned long long b, unsigned long long c) {
    unsigned long long d;
    asm("fma.rn.f32x2 %0, %1, %2, %3;" : "=l"(d) : "l"(a), "l"(b), "l"(c));
    return d;
}
__device__ __forceinline__ unsigned long long add2(unsigned long long a, unsigned long long b) {
    unsigned long long d;
    asm("add.rn.f32x2 %0, %1, %2;" : "=l"(d) : "l"(a), "l"(b));
    return d;
}
__device__ __forceinline__ float ex2f(float x) {
    float y; asm("ex2.approx.f32 %0, %1;" : "=f"(y) : "f"(x)); return y;
}
__device__ __forceinline__ float lg2f(float x) {
    float y; asm("lg2.approx.f32 %0, %1;" : "=f"(y) : "f"(x)); return y;
}
__device__ __forceinline__ float rcpf(float x) {
    float y; asm("rcp.approx.f32 %0, %1;" : "=f"(y) : "f"(x)); return y;
}

#define LOG2E 1.4426950408889634f
#define LN2   0.6931471805599453f

// Half-split matvec: lane loads only its 16-value half of w (4x LDS.128),
// computes partials for output j (ea) and partner output j^16 (eb), then one
// shfl.xor(16) completes both dot products. Halves LDS slot+wavefront cost
// vs the full 8-LDS matvec (R14 analysis: loop is SMSP-issue-slot bound).
__device__ __forceinline__ float matvec_half(const float* wb_half,
                                             const unsigned long long* ea,
                                             const unsigned long long* eb) {
    const ulonglong2* w4 = (const ulonglong2*)wb_half;
    ulonglong2 q0 = w4[0], q1 = w4[1];
    unsigned long long pa0 = mul2(q0.x, ea[0]);
    unsigned long long pa1 = mul2(q0.y, ea[1]);
    unsigned long long pb0 = mul2(q0.x, eb[0]);
    unsigned long long pb1 = mul2(q0.y, eb[1]);
    pa0 = fma2(q1.x, ea[2], pa0);
    pa1 = fma2(q1.y, ea[3], pa1);
    pb0 = fma2(q1.x, eb[2], pb0);
    pb1 = fma2(q1.y, eb[3], pb1);
    ulonglong2 q2 = w4[2], q3 = w4[3];
    pa0 = fma2(q2.x, ea[4], pa0);
    pa1 = fma2(q2.y, ea[5], pa1);
    pb0 = fma2(q2.x, eb[4], pb0);
    pb1 = fma2(q2.y, eb[5], pb1);
    pa0 = fma2(q3.x, ea[6], pa0);
    pa1 = fma2(q3.y, ea[7], pa1);
    pb0 = fma2(q3.x, eb[6], pb0);
    pb1 = fma2(q3.y, eb[7], pb1);
    pa0 = add2(pa0, pa1);
    pb0 = add2(pb0, pb1);
    float al, ah, bl, bh;
    upk2(pa0, al, ah);
    upk2(pb0, bl, bh);
    float fa = al + ah;                 // my-half partial for output j
    float fb = bl + bh;                 // my-half partial for output j^16
    // partner's fb IS the other-half partial for my output j
    return fa + __shfl_xor_sync(0xffffffffu, fb, 16);
}

// ---------------------------------------------------------------------------
// Forward+backward kernel: 1 chain per warp, 2048 warps (best measured shape).
// 2 batches per block (128 threads):
//   warp 0: fwd b0   warp 1: bwd b0   warp 2: fwd b1   warp 3: bwd b1
// Prob-space recursion, renorm every 4 steps via off-path shfl(u,0).
// Meet: Z = sum_k (E^T alpha_511)_k gamma_512(k)
// ---------------------------------------------------------------------------
__global__ __launch_bounds__(128, 4)
void crf_fb_kernel(const float* __restrict__ logits,
                   const float* __restrict__ trans) {
    const int w   = threadIdx.x >> 5;     // warp in block (0..3)
    const int j   = threadIdx.x & 31;     // lane = tag
    const int bi  = w >> 1;               // batch within block (0/1)
    const int dir = w & 1;                // 0 = fwd, 1 = bwd
    const int b   = blockIdx.x * 2 + bi;

    __shared__ __align__(16) float sbuf[4][2][32];  // [warp][parity][vec]
    __shared__ float xg[2][32];                     // gamma_512 exchange
    __shared__ float xacc[2];                       // bwd log-scale exchange

    const int h  = (j >> 4) << 4;         // my half's base index (0 or 16)
    const int jp = j ^ 16;                // partner output tag

    // E operand registers for the half-split matvec:
    //  fwd (sum over i for output col): ea[k] = {E[h+2k][j],  E[h+2k+1][j]}
    //                                   eb[k] = {E[h+2k][jp], E[h+2k+1][jp]}
    //  bwd (sum over cols for row):     ea[k] = {E[j][h+2k],  E[j][h+2k+1]}
    //                                   eb[k] = {E[jp][h+2k], E[jp][h+2k+1]}
    unsigned long long ea[8], eb[8];
    if (dir == 0) {
#pragma unroll
        for (int k = 0; k < 8; k++) {
            ea[k] = pk2(expf(trans[(h + 2 * k) * TAGS + j]),
                        expf(trans[(h + 2 * k + 1) * TAGS + j]));
            eb[k] = pk2(expf(trans[(h + 2 * k) * TAGS + jp]),
                        expf(trans[(h + 2 * k + 1) * TAGS + jp]));
        }
    } else {
#pragma unroll
        for (int k = 0; k < 8; k++) {
            ea[k] = pk2(expf(trans[j * TAGS + h + 2 * k]),
                        expf(trans[j * TAGS + h + 2 * k + 1]));
            eb[k] = pk2(expf(trans[jp * TAGS + h + 2 * k]),
                        expf(trans[jp * TAGS + h + 2 * k + 1]));
        }
    }

    const float* lg = logits + (size_t)b * (SEQ * TAGS);

    // init state (scaled by lane-0 emit)
    float e0 = (dir == 0) ? lg[j] : lg[(SEQ - 1) * TAGS + j];
    float m0 = __shfl_sync(0xffffffffu, e0, 0);
    float u      = ex2f((e0 - m0) * LOG2E);
    float logacc = m0;

    // emit stream: fwd rows 1..511, bwd rows 1022..512.
    // Ring depth PF=8; tail over-reads stay in-bounds (fwd<=519, bwd>=504).
    const int estep = (dir == 0) ? TAGS : -TAGS;
    const float* ep = (dir == 0) ? (lg + TAGS + j)
                                 : (lg + (SEQ - 2) * TAGS + j);
    float r[PF];
#pragma unroll
    for (int k = 0; k < PF; k++)
        r[k] = ep[k * estep];
    const float* pl = ep + PF * estep;

    float* wb0 = &sbuf[w][0][0];
    float* wb1 = &sbuf[w][1][0];

#pragma unroll 8
    for (int it = 0; it < ITERS; ++it) {
        // renorm scale: off-path shfl of current u, result used only at the
        // very end of the iteration (slack >> shfl latency)
        float u0 = 0.0f;
        if ((it & 3) == 0)
            u0 = __shfl_sync(0xffffffffu, u, 0);

        float emit = r[it & (PF - 1)];
        r[it & (PF - 1)] = *pl;             // refill same slot (needed it+8)
        pl += estep;

        float p = ex2f(emit * LOG2E);       // off the carried chain

        float* wb = (it & 1) ? wb1 : wb0;
        wb[j] = u;
        __syncwarp(0xffffffffu);

        float s = matvec_half(wb + h, ea, eb);
        float un = s * p;

        if ((it & 3) == 0) {
            un *= rcpf(u0);
            logacc += lg2f(u0) * LN2;       // off-path bookkeeping
        }
        u = un;
    }

    // final renorm so the meeting dot-product can't overflow
    {
        float u0 = __shfl_sync(0xffffffffu, u, 0);
        u *= rcpf(u0);
        logacc += lg2f(u0) * LN2;
    }

    if (dir == 1) {
        xg[bi][j] = u;                      // gamma_512 (scaled)
        if (j == 0) xacc[bi] = logacc;
    }
    __syncthreads();

    if (dir == 0) {
        // s = E^T alpha_511 (one more matvec, no emit). Parity-1 buffer:
        // its last reads (it=509) are sealed by syncwarp(it=510).
        wb1[j] = u;
        __syncwarp(0xffffffffu);
        float s = matvec_half(wb1 + h, ea, eb);

        float prod = s * xg[bi][j];
#pragma unroll
        for (int k = 16; k; k >>= 1)
            prod += __shfl_xor_sync(0xffffffffu, prod, k);

        if (j == 0)
            g_logz[b] = lg2f(prod) * LN2 + logacc + xacc[bi];
    }
}

// ---------------------------------------------------------------------------
// Gold score: one 256-thread block per batch (gather-latency hiding). Last
// block performs the ticket-fenced deterministic reduction -> mean.
// ---------------------------------------------------------------------------
__global__ __launch_bounds__(256, 4)
void crf_gold_reduce_kernel(const float* __restrict__ logits,
                            const float* __restrict__ trans,
                            const int* __restrict__ tags,
                            const int* __restrict__ lengths,
                            float* __restrict__ out) {
    __shared__ float tr[TAGS * TAGS];
    __shared__ float sm[8];
    __shared__ bool  amLast;

    for (int i = threadIdx.x; i < TAGS * TAGS; i += blockDim.x)
        tr[i] = trans[i];
    __syncthreads();

    const int b    = blockIdx.x;
    const int tid  = threadIdx.x;
    const int warp = tid >> 5;
    const int l    = tid & 31;

    const int*   tg = tags + (size_t)b * SEQ;
    const float* lg = logits + (size_t)b * (SEQ * TAGS);
    const int len = lengths[b];

    float acc = 0.0f;
    for (int s = tid; s < len; s += 256) {
        int t1 = __ldg(&tg[s]);
        acc += __ldg(&lg[s * TAGS + t1]);
        if (s > 0) {
            int t0 = __ldg(&tg[s - 1]);
            acc += tr[t0 * TAGS + t1];
        }
    }
#pragma unroll
    for (int k = 16; k; k >>= 1)
        acc += __shfl_xor_sync(0xffffffffu, acc, k);
    if (l == 0) sm[warp] = acc;
    __syncthreads();

    if (tid == 0) {
        float gold = 0.0f;
#pragma unroll
        for (int q = 0; q < 8; q++) gold += sm[q];
        g_partial[b] = g_logz[b] - gold;
        __threadfence();
        unsigned int t = atomicAdd(&g_ticket, 1u);
        amLast = (t == (unsigned)(BATCH - 1));
    }
    __syncthreads();

    if (amLast) {
        __shared__ float red[256];
        float a = 0.0f;
#pragma unroll
        for (int o = 0; o < 4; o++)
            a += __ldcg(&g_partial[tid + o * 256]);
        red[tid] = a;
        __syncthreads();
#pragma unroll
        for (int k = 128; k; k >>= 1) {
            if (tid < k) red[tid] += red[tid + k];
            __syncthreads();
        }
        if (tid == 0) {
            out[0] = red[0] * (1.0f / 1024.0f);
            g_ticket = 0;                  // reset for next graph replay
        }
    }
}

extern "C" void kernel_launch(void* const* d_in, const int* in_sizes, int n_in,
                              void* d_out, int out_size) {
    const float* logits  = (const float*)d_in[0];
    const float* trans   = (const float*)d_in[1];
    const int*   tags    = (const int*)d_in[2];
    const int*   lengths = (const int*)d_in[3];
    float* out = (float*)d_out;

    crf_fb_kernel<<<BATCH / 2, 128>>>(logits, trans);
    crf_gold_reduce_kernel<<<BATCH, 256>>>(logits, trans, tags, lengths, out);
}